// round 4
// baseline (speedup 1.0000x reference)
#include <cuda_runtime.h>
#include <math.h>

#define TT 4096
#define DD 4096
#define VV 32000
#define PRE_BLOCKS 2048  // 2 timesteps per block, 256 threads
#define MOM_BLOCKS 11    // one block per j-power

// ---------------- scratch (device globals; no allocations) ----------------
__device__ float g_pre0[TT];
__device__ float g_pre1[TT];
__device__ float g_h0[TT];
__device__ float g_h1[TT];
__device__ float g_C[121];

__device__ __constant__ float c_invfact[11] = {
    1.0f, 1.0f, 0.5f, 1.6666667e-1f, 4.1666668e-2f, 8.3333338e-3f,
    1.3888889e-3f, 1.9841270e-4f, 2.4801588e-5f, 2.7557319e-6f, 2.7557319e-7f
};

// accurate-enough tanh: exact +-1 in saturation (matches fp32 tanh rounding),
// ~1e-7 error elsewhere (EX2 + RCP)
__device__ __forceinline__ float tanh_acc(float a) {
    float ab = fabsf(a);
    if (ab > 9.1f) return copysignf(1.0f, a);
    float e = __expf(-2.0f * ab);
    float r = __fdividef(1.0f - e, 1.0f + e);
    return copysignf(r, a);
}

// ---------------- K1: pre-GEMV (2 rows/block, max MLP) + Taylor moments ------
__global__ __launch_bounds__(256) void k1_pre_moments(const float* __restrict__ x,
                                                      const float* __restrict__ Wih,
                                                      const float* __restrict__ bih,
                                                      const float* __restrict__ bhh,
                                                      const float* __restrict__ Wfc,
                                                      const float* __restrict__ bfc) {
    int b = blockIdx.x;
    int tid = threadIdx.x;

    if (b < PRE_BLOCKS) {
        // ---- rows t0, t0+1: each thread does 4 float4 per row, 16 loads in flight
        int t0 = b * 2;
        const float4* xa = (const float4*)(x + (size_t)t0 * DD);
        const float4* xb = xa + DD / 4;
        const float4* w0 = (const float4*)(Wih);
        const float4* w1 = (const float4*)(Wih + DD);

        float a00 = 0.f, a01 = 0.f, a10 = 0.f, a11 = 0.f;
#pragma unroll
        for (int k = 0; k < 4; k++) {
            int i = tid + k * 256;
            float4 va = __ldcs(&xa[i]);
            float4 vb = __ldcs(&xb[i]);
            float4 u0 = __ldg(&w0[i]);
            float4 u1 = __ldg(&w1[i]);
            a00 = fmaf(va.x, u0.x, a00); a00 = fmaf(va.y, u0.y, a00);
            a00 = fmaf(va.z, u0.z, a00); a00 = fmaf(va.w, u0.w, a00);
            a01 = fmaf(va.x, u1.x, a01); a01 = fmaf(va.y, u1.y, a01);
            a01 = fmaf(va.z, u1.z, a01); a01 = fmaf(va.w, u1.w, a01);
            a10 = fmaf(vb.x, u0.x, a10); a10 = fmaf(vb.y, u0.y, a10);
            a10 = fmaf(vb.z, u0.z, a10); a10 = fmaf(vb.w, u0.w, a10);
            a11 = fmaf(vb.x, u1.x, a11); a11 = fmaf(vb.y, u1.y, a11);
            a11 = fmaf(vb.z, u1.z, a11); a11 = fmaf(vb.w, u1.w, a11);
        }
#pragma unroll
        for (int o = 16; o; o >>= 1) {
            a00 += __shfl_down_sync(0xffffffffu, a00, o);
            a01 += __shfl_down_sync(0xffffffffu, a01, o);
            a10 += __shfl_down_sync(0xffffffffu, a10, o);
            a11 += __shfl_down_sync(0xffffffffu, a11, o);
        }
        __shared__ float4 sred[8];
        if ((tid & 31) == 0) sred[tid >> 5] = make_float4(a00, a01, a10, a11);
        __syncthreads();
        if (tid < 8) {
            float4 v = sred[tid];
            float s00 = v.x, s01 = v.y, s10 = v.z, s11 = v.w;
#pragma unroll
            for (int o = 4; o; o >>= 1) {
                s00 += __shfl_down_sync(0xffu, s00, o);
                s01 += __shfl_down_sync(0xffu, s01, o);
                s10 += __shfl_down_sync(0xffu, s10, o);
                s11 += __shfl_down_sync(0xffu, s11, o);
            }
            if (tid == 0) {
                float c0 = bih[0] + bhh[0];
                float c1 = bih[1] + bhh[1];
                g_pre0[t0]     = s00 + c0;
                g_pre1[t0]     = s01 + c1;
                g_pre0[t0 + 1] = s10 + c0;
                g_pre1[t0 + 1] = s11 + c1;
            }
        }
    } else {
        // ---- moments: block j computes C_jk for all k (11 accumulators) ----
        int j = b - PRE_BLOCKS;     // 0..10
        float acc[11];
#pragma unroll
        for (int k = 0; k < 11; k++) acc[k] = 0.f;

        for (int v = tid; v < VV; v += 256) {
            float2 w = *(const float2*)(Wfc + 2 * v);
            float p = __expf(bfc[v]);
#pragma unroll
            for (int a = 0; a < 10; a++) {
                if (a < j) p *= w.x;
            }
#pragma unroll
            for (int k = 0; k < 11; k++) {
                acc[k] += p;
                p *= w.y;
            }
        }
        __shared__ float sredm[8][11];
#pragma unroll
        for (int k = 0; k < 11; k++) {
#pragma unroll
            for (int o = 16; o; o >>= 1)
                acc[k] += __shfl_down_sync(0xffffffffu, acc[k], o);
        }
        if ((tid & 31) == 0) {
#pragma unroll
            for (int k = 0; k < 11; k++) sredm[tid >> 5][k] = acc[k];
        }
        __syncthreads();
        if (tid < 11) {
            float tot = 0.f;
#pragma unroll
            for (int w = 0; w < 8; w++) tot += sredm[w][tid];
            g_C[j * 11 + tid] = tot * c_invfact[j] * c_invfact[tid];
        }
    }
}

// ---------------- K2: segmented scan, single block, pre staged in SMEM -------
__global__ __launch_bounds__(1024) void k2_scan(const float* __restrict__ Whh) {
    __shared__ float sp0[TT];
    __shared__ float sp1[TT];
    int tid = threadIdx.x;
    for (int i = tid; i < TT; i += 1024) {
        sp0[i] = g_pre0[i];
        sp1[i] = g_pre1[i];
    }
    __syncthreads();

    float W00 = Whh[0], W01 = Whh[1], W10 = Whh[2], W11 = Whh[3];
    float th0 = 9.2f + fabsf(W00) + fabsf(W01);
    float th1 = 9.2f + fabsf(W10) + fabsf(W11);

#pragma unroll
    for (int k = 0; k < 5; k++) {
        int idx = tid + k * 1024;           // starter index 0..TT
        if (k == 4 && tid != 0) break;      // only thread 0 handles idx==TT
        if (k == 4) idx = TT;

        float h0, h1;
        int t;
        if (idx == 0) {
            h0 = 0.f; h1 = 0.f; t = 0;
        } else {
            int r = idx - 1;
            float p0 = sp0[r], p1 = sp1[r];
            if (!(fabsf(p0) > th0 && fabsf(p1) > th1)) continue;  // not a reset point
            h0 = copysignf(1.0f, p0);   // saturated: tanh == +-1.0f exactly
            h1 = copysignf(1.0f, p1);
            g_h0[r] = h0;
            g_h1[r] = h1;
            t = r + 1;
        }
        while (t < TT) {
            float p0 = sp0[t], p1 = sp1[t];
            if (fabsf(p0) > th0 && fabsf(p1) > th1) break;  // next reset owns t
            float a0 = fmaf(W01, h1, fmaf(W00, h0, p0));
            float a1 = fmaf(W11, h1, fmaf(W10, h0, p1));
            h0 = tanh_acc(a0);
            h1 = tanh_acc(a1);
            g_h0[t] = h0;
            g_h1[t] = h1;
            t++;
        }
    }
}

// ---------------- K3: logits (HBM-write bound, 32-row tiles) + loss fused ----
// logits blocks: b in [0, 1024): t-tile = (b & 127)*32, v-chunk = (b >> 7)*4000
// loss block: b == n_logit_blocks
__global__ __launch_bounds__(256) void k3_logits_loss(const float* __restrict__ Wfc,
                                                      const float* __restrict__ bfc,
                                                      const int* __restrict__ tgt_raw,
                                                      float* __restrict__ out,
                                                      long long loss_idx,
                                                      int n_logit_blocks) {
    int b = blockIdx.x;
    int tid = threadIdx.x;

    if (b < n_logit_blocks) {
        // ------------- logits -------------
        __shared__ float sh0[32], sh1[32];
        int tb = (b & 127) * 32;
        if (tid < 32) {
            sh0[tid] = g_h0[tb + tid];
            sh1[tid] = g_h1[tb + tid];
        }
        __syncthreads();
        float h0r[32], h1r[32];
#pragma unroll
        for (int r = 0; r < 32; r++) { h0r[r] = sh0[r]; h1r[r] = sh1[r]; }

        const int vbeg = (b >> 7) * 4000;
        const int vend = vbeg + 4000;
        for (int v = vbeg + tid * 4; v < vend; v += 1024) {
            float4 wa = *(const float4*)(Wfc + 2 * v);      // w0,w1 of v, v+1
            float4 wb = *(const float4*)(Wfc + 2 * v + 4);  // w0,w1 of v+2, v+3
            float4 bb = *(const float4*)(bfc + v);
            float* op = out + (size_t)tb * VV + v;
#pragma unroll
            for (int r = 0; r < 32; r++) {
                float4 o;
                o.x = fmaf(h0r[r], wa.x, fmaf(h1r[r], wa.y, bb.x));
                o.y = fmaf(h0r[r], wa.z, fmaf(h1r[r], wa.w, bb.y));
                o.z = fmaf(h0r[r], wb.x, fmaf(h1r[r], wb.y, bb.z));
                o.w = fmaf(h0r[r], wb.z, fmaf(h1r[r], wb.w, bb.w));
                __stcs((float4*)(op + (size_t)r * VV), o);
            }
        }
    } else {
        // ------------- loss (runs concurrently with logits blocks) -------------
        __shared__ float sC[121];
        if (tid < 121) sC[tid] = g_C[tid];

        // detect int64 vs int32 targets: int64 (LE) => all odd 32-bit words of
        // the first 4096 words are zero (values < 32000). OOB-safe either way.
        int local = 0;
        for (int i = tid; i < TT / 2; i += 256) local |= tgt_raw[2 * i + 1];
        int nz = __syncthreads_or(local);
        int is64 = (nz == 0);

        float acc = 0.f;
#pragma unroll
        for (int r = 0; r < 16; r++) {
            int t = r * 256 + tid;
            float h0 = g_h0[t];
            float h1 = g_h1[t];
            // sumexp(h) = sum_{j,k<=10} C_jk h0^j h1^k (double Horner)
            float S = 0.f;
#pragma unroll
            for (int j = 10; j >= 0; j--) {
                const float* row = &sC[j * 11];
                float inner = row[10];
#pragma unroll
                for (int k = 9; k >= 0; k--) inner = fmaf(inner, h1, row[k]);
                S = fmaf(S, h0, inner);
            }
            int g = is64 ? tgt_raw[2 * t] : tgt_raw[t];
            float lt = fmaf(h0, Wfc[2 * g], fmaf(h1, Wfc[2 * g + 1], bfc[g]));
            acc += logf(S) - lt;
        }

#pragma unroll
        for (int o = 16; o; o >>= 1) acc += __shfl_down_sync(0xffffffffu, acc, o);
        __shared__ float s[8];
        if ((tid & 31) == 0) s[tid >> 5] = acc;
        __syncthreads();
        if (tid == 0) {
            float tot = 0.f;
#pragma unroll
            for (int w = 0; w < 8; w++) tot += s[w];
            if (loss_idx >= 0) out[loss_idx] = tot * (1.0f / TT);
        }
    }
}

// ---------------- launch ----------------
extern "C" void kernel_launch(void* const* d_in, const int* in_sizes, int n_in,
                              void* d_out, int out_size) {
    const float* x       = (const float*)d_in[0];
    const int*   targets = (const int*)d_in[1];   // int32 or int64, detected on device
    const float* Wih     = (const float*)d_in[2];
    const float* bih     = (const float*)d_in[3];
    const float* Whh     = (const float*)d_in[4];
    const float* bhh     = (const float*)d_in[5];
    const float* Wfc     = (const float*)d_in[6];
    const float* bfc     = (const float*)d_in[7];
    float* out = (float*)d_out;

    const long long logits_elems = (long long)TT * VV;

    k1_pre_moments<<<PRE_BLOCKS + MOM_BLOCKS, 256>>>(x, Wih, bih, bhh, Wfc, bfc);
    k2_scan<<<1, 1024>>>(Whh);

    int n_logit_blocks = ((long long)out_size >= logits_elems) ? 1024 : 0;
    long long loss_idx = -1;
    if ((long long)out_size > logits_elems) loss_idx = logits_elems;  // logits + loss
    else if (out_size == 1) loss_idx = 0;                             // loss only
    k3_logits_loss<<<n_logit_blocks + 1, 256>>>(Wfc, bfc, targets, out,
                                                loss_idx, n_logit_blocks);
}

// round 5
// speedup vs baseline: 1.1667x; 1.1667x over previous
#include <cuda_runtime.h>
#include <math.h>

#define TT 4096
#define DD 4096
#define VV 32000
#define NCHUNK 4                       // D split into 4 chunks of 1024 floats
#define ROWS_PB 8                      // rows per pre-block
#define PRE_BLOCKS ((TT / ROWS_PB) * NCHUNK)   // 2048
#define MOM_BLOCKS (11 * 4)            // j x v-chunk

// ---------------- scratch (device globals; no allocations) ----------------
__device__ float g_part[NCHUNK * TT * 2];   // partial pre sums, [chunk][t][h]
__device__ float g_h0[TT];
__device__ float g_h1[TT];
__device__ float g_Cm[4 * 121];             // moment partials per v-chunk

__device__ __constant__ float c_invfact[11] = {
    1.0f, 1.0f, 0.5f, 1.6666667e-1f, 4.1666668e-2f, 8.3333338e-3f,
    1.3888889e-3f, 1.9841270e-4f, 2.4801588e-5f, 2.7557319e-6f, 2.7557319e-7f
};

// accurate-enough tanh: exact +-1 in saturation (matches fp32 tanh rounding),
// ~1e-7 error elsewhere (EX2 + RCP)
__device__ __forceinline__ float tanh_acc(float a) {
    float ab = fabsf(a);
    if (ab > 9.1f) return copysignf(1.0f, a);
    float e = __expf(-2.0f * ab);
    float r = __fdividef(1.0f - e, 1.0f + e);
    return copysignf(r, a);
}

// ---------------- K1: pre-GEMV partials (8 rows/thread-column) + moments -----
__global__ __launch_bounds__(256) void k1_pre_moments(const float* __restrict__ x,
                                                      const float* __restrict__ Wih,
                                                      const float* __restrict__ Wfc,
                                                      const float* __restrict__ bfc) {
    int b = blockIdx.x;
    int tid = threadIdx.x;

    if (b < PRE_BLOCKS) {
        int rt = b >> 2;                 // row tile (0..511)
        int c  = b & 3;                  // D-chunk (0..3)
        int t0 = rt * ROWS_PB;
        int i  = c * 256 + tid;          // float4 column index within row (0..1023)

        const float4* w0g = (const float4*)(Wih);
        const float4* w1g = (const float4*)(Wih + DD);
        float4 w0 = __ldg(&w0g[i]);
        float4 w1 = __ldg(&w1g[i]);

        // 8 independent streaming loads, front-batched for MLP
        float4 xv[ROWS_PB];
        const float4* xb = (const float4*)(x) + (size_t)t0 * (DD / 4) + i;
#pragma unroll
        for (int r = 0; r < ROWS_PB; r++) xv[r] = __ldcs(xb + (size_t)r * (DD / 4));

        float a0[ROWS_PB], a1[ROWS_PB];
#pragma unroll
        for (int r = 0; r < ROWS_PB; r++) {
            float4 v = xv[r];
            a0[r] = fmaf(v.x, w0.x, fmaf(v.y, w0.y, fmaf(v.z, w0.z, v.w * w0.w)));
            a1[r] = fmaf(v.x, w1.x, fmaf(v.y, w1.y, fmaf(v.z, w1.z, v.w * w1.w)));
        }

        // warp reduce 16 values
#pragma unroll
        for (int o = 16; o; o >>= 1) {
#pragma unroll
            for (int r = 0; r < ROWS_PB; r++) {
                a0[r] += __shfl_down_sync(0xffffffffu, a0[r], o);
                a1[r] += __shfl_down_sync(0xffffffffu, a1[r], o);
            }
        }
        __shared__ float sred[8][16];
        int wid = tid >> 5, lid = tid & 31;
        if (lid == 0) {
#pragma unroll
            for (int r = 0; r < ROWS_PB; r++) {
                sred[wid][2 * r]     = a0[r];
                sred[wid][2 * r + 1] = a1[r];
            }
        }
        __syncthreads();
        if (tid < 16) {
            float s = 0.f;
#pragma unroll
            for (int w = 0; w < 8; w++) s += sred[w][tid];
            int r = tid >> 1, h = tid & 1;
            g_part[((size_t)c * TT + t0 + r) * 2 + h] = s;
        }
    } else {
        // ---- moments partials: block (j, vc), each covers V/4 elements ----
        int m = b - PRE_BLOCKS;
        int j  = m >> 2;                 // 0..10
        int vc = m & 3;                  // 0..3
        float acc[11];
#pragma unroll
        for (int k = 0; k < 11; k++) acc[k] = 0.f;

        int vbeg = vc * (VV / 4), vend = vbeg + (VV / 4);
        for (int v = vbeg + tid; v < vend; v += 256) {
            float2 w = *(const float2*)(Wfc + 2 * v);
            float p = __expf(bfc[v]);
#pragma unroll
            for (int a = 0; a < 10; a++) {
                if (a < j) p *= w.x;
            }
#pragma unroll
            for (int k = 0; k < 11; k++) {
                acc[k] += p;
                p *= w.y;
            }
        }
        __shared__ float sredm[8][11];
#pragma unroll
        for (int k = 0; k < 11; k++) {
#pragma unroll
            for (int o = 16; o; o >>= 1)
                acc[k] += __shfl_down_sync(0xffffffffu, acc[k], o);
        }
        if ((tid & 31) == 0) {
#pragma unroll
            for (int k = 0; k < 11; k++) sredm[tid >> 5][k] = acc[k];
        }
        __syncthreads();
        if (tid < 11) {
            float tot = 0.f;
#pragma unroll
            for (int w = 0; w < 8; w++) tot += sredm[w][tid];
            g_Cm[vc * 121 + j * 11 + tid] = tot * c_invfact[j] * c_invfact[tid];
        }
    }
}

// ---------------- K2: sum partials + biases, segmented scan in SMEM ----------
__global__ __launch_bounds__(1024) void k2_scan(const float* __restrict__ Whh,
                                                const float* __restrict__ bih,
                                                const float* __restrict__ bhh) {
    __shared__ float sp0[TT];
    __shared__ float sp1[TT];
    int tid = threadIdx.x;
    float c0 = bih[0] + bhh[0];
    float c1 = bih[1] + bhh[1];
    for (int i = tid; i < TT; i += 1024) {
        float p0 = c0, p1 = c1;
#pragma unroll
        for (int c = 0; c < NCHUNK; c++) {
            p0 += g_part[((size_t)c * TT + i) * 2 + 0];
            p1 += g_part[((size_t)c * TT + i) * 2 + 1];
        }
        sp0[i] = p0;
        sp1[i] = p1;
    }
    __syncthreads();

    float W00 = Whh[0], W01 = Whh[1], W10 = Whh[2], W11 = Whh[3];
    float th0 = 9.2f + fabsf(W00) + fabsf(W01);
    float th1 = 9.2f + fabsf(W10) + fabsf(W11);

#pragma unroll
    for (int k = 0; k < 5; k++) {
        int idx = tid + k * 1024;           // starter index 0..TT
        if (k == 4 && tid != 0) break;      // only thread 0 handles idx==TT
        if (k == 4) idx = TT;

        float h0, h1;
        int t;
        if (idx == 0) {
            h0 = 0.f; h1 = 0.f; t = 0;
        } else {
            int r = idx - 1;
            float p0 = sp0[r], p1 = sp1[r];
            if (!(fabsf(p0) > th0 && fabsf(p1) > th1)) continue;  // not a reset point
            h0 = copysignf(1.0f, p0);   // saturated: tanh == +-1.0f exactly
            h1 = copysignf(1.0f, p1);
            g_h0[r] = h0;
            g_h1[r] = h1;
            t = r + 1;
        }
        while (t < TT) {
            float p0 = sp0[t], p1 = sp1[t];
            if (fabsf(p0) > th0 && fabsf(p1) > th1) break;  // next reset owns t
            float a0 = fmaf(W01, h1, fmaf(W00, h0, p0));
            float a1 = fmaf(W11, h1, fmaf(W10, h0, p1));
            h0 = tanh_acc(a0);
            h1 = tanh_acc(a1);
            g_h0[t] = h0;
            g_h1[t] = h1;
            t++;
        }
    }
}

// ---------------- K3: logits (HBM-write bound, 32-row tiles) + loss fused ----
__global__ __launch_bounds__(256) void k3_logits_loss(const float* __restrict__ Wfc,
                                                      const float* __restrict__ bfc,
                                                      const int* __restrict__ tgt_raw,
                                                      float* __restrict__ out,
                                                      long long loss_idx,
                                                      int n_logit_blocks) {
    int b = blockIdx.x;
    int tid = threadIdx.x;

    if (b < n_logit_blocks) {
        // ------------- logits -------------
        __shared__ float sh0[32], sh1[32];
        int tb = (b & 127) * 32;
        if (tid < 32) {
            sh0[tid] = g_h0[tb + tid];
            sh1[tid] = g_h1[tb + tid];
        }
        __syncthreads();
        float h0r[32], h1r[32];
#pragma unroll
        for (int r = 0; r < 32; r++) { h0r[r] = sh0[r]; h1r[r] = sh1[r]; }

        const int vbeg = (b >> 7) * 4000;
        const int vend = vbeg + 4000;
        for (int v = vbeg + tid * 4; v < vend; v += 1024) {
            float4 wa = *(const float4*)(Wfc + 2 * v);      // w0,w1 of v, v+1
            float4 wb = *(const float4*)(Wfc + 2 * v + 4);  // w0,w1 of v+2, v+3
            float4 bb = *(const float4*)(bfc + v);
            float* op = out + (size_t)tb * VV + v;
#pragma unroll
            for (int r = 0; r < 32; r++) {
                float4 o;
                o.x = fmaf(h0r[r], wa.x, fmaf(h1r[r], wa.y, bb.x));
                o.y = fmaf(h0r[r], wa.z, fmaf(h1r[r], wa.w, bb.y));
                o.z = fmaf(h0r[r], wb.x, fmaf(h1r[r], wb.y, bb.z));
                o.w = fmaf(h0r[r], wb.z, fmaf(h1r[r], wb.w, bb.w));
                __stcs((float4*)(op + (size_t)r * VV), o);
            }
        }
    } else {
        // ------------- loss (runs concurrently with logits blocks) -------------
        __shared__ float sC[121];
        if (tid < 121)
            sC[tid] = g_Cm[tid] + g_Cm[121 + tid] + g_Cm[242 + tid] + g_Cm[363 + tid];

        // detect int64 vs int32 targets: int64 (LE) => all odd 32-bit words of
        // the first 4096 words are zero (values < 32000). OOB-safe either way.
        int local = 0;
        for (int i = tid; i < TT / 2; i += 256) local |= tgt_raw[2 * i + 1];
        int nz = __syncthreads_or(local);
        int is64 = (nz == 0);

        float acc = 0.f;
#pragma unroll
        for (int r = 0; r < 16; r++) {
            int t = r * 256 + tid;
            float h0 = g_h0[t];
            float h1 = g_h1[t];
            // sumexp(h) = sum_{j,k<=10} C_jk h0^j h1^k (double Horner)
            float S = 0.f;
#pragma unroll
            for (int j = 10; j >= 0; j--) {
                const float* row = &sC[j * 11];
                float inner = row[10];
#pragma unroll
                for (int k = 9; k >= 0; k--) inner = fmaf(inner, h1, row[k]);
                S = fmaf(S, h0, inner);
            }
            int g = is64 ? tgt_raw[2 * t] : tgt_raw[t];
            float lt = fmaf(h0, Wfc[2 * g], fmaf(h1, Wfc[2 * g + 1], bfc[g]));
            acc += logf(S) - lt;
        }

#pragma unroll
        for (int o = 16; o; o >>= 1) acc += __shfl_down_sync(0xffffffffu, acc, o);
        __shared__ float s[8];
        if ((tid & 31) == 0) s[tid >> 5] = acc;
        __syncthreads();
        if (tid == 0) {
            float tot = 0.f;
#pragma unroll
            for (int w = 0; w < 8; w++) tot += s[w];
            if (loss_idx >= 0) out[loss_idx] = tot * (1.0f / TT);
        }
    }
}

// ---------------- launch ----------------
extern "C" void kernel_launch(void* const* d_in, const int* in_sizes, int n_in,
                              void* d_out, int out_size) {
    const float* x       = (const float*)d_in[0];
    const int*   targets = (const int*)d_in[1];   // int32 or int64, detected on device
    const float* Wih     = (const float*)d_in[2];
    const float* bih     = (const float*)d_in[3];
    const float* Whh     = (const float*)d_in[4];
    const float* bhh     = (const float*)d_in[5];
    const float* Wfc     = (const float*)d_in[6];
    const float* bfc     = (const float*)d_in[7];
    float* out = (float*)d_out;

    const long long logits_elems = (long long)TT * VV;

    k1_pre_moments<<<PRE_BLOCKS + MOM_BLOCKS, 256>>>(x, Wih, Wfc, bfc);
    k2_scan<<<1, 1024>>>(Whh, bih, bhh);

    int n_logit_blocks = ((long long)out_size >= logits_elems) ? 1024 : 0;
    long long loss_idx = -1;
    if ((long long)out_size > logits_elems) loss_idx = logits_elems;  // logits + loss
    else if (out_size == 1) loss_idx = 0;                             // loss only
    k3_logits_loss<<<n_logit_blocks + 1, 256>>>(Wfc, bfc, targets, out,
                                                loss_idx, n_logit_blocks);
}

// round 6
// speedup vs baseline: 1.1991x; 1.0277x over previous
#include <cuda_runtime.h>
#include <math.h>

#define TT 4096
#define DD 4096
#define VV 32000
#define NCHUNK 4                       // D split into 4 chunks of 1024 floats
#define ROWS_PB 16                     // rows per pre-block
#define PRE_BLOCKS ((TT / ROWS_PB) * NCHUNK)   // 1024
#define MOM_BLOCKS (11 * 4)            // j x v-chunk

// ---------------- scratch (device globals; no allocations) ----------------
__device__ float g_part[NCHUNK * TT * 2];   // partial pre sums, [chunk][t][h]
__device__ float g_h0[TT];
__device__ float g_h1[TT];
__device__ float g_Cm[4 * 121];             // moment partials per v-chunk

__device__ __constant__ float c_invfact[11] = {
    1.0f, 1.0f, 0.5f, 1.6666667e-1f, 4.1666668e-2f, 8.3333338e-3f,
    1.3888889e-3f, 1.9841270e-4f, 2.4801588e-5f, 2.7557319e-6f, 2.7557319e-7f
};

// accurate-enough tanh: exact +-1 in saturation (matches fp32 tanh rounding),
// ~1e-7 error elsewhere (EX2 + RCP)
__device__ __forceinline__ float tanh_acc(float a) {
    float ab = fabsf(a);
    if (ab > 9.1f) return copysignf(1.0f, a);
    float e = __expf(-2.0f * ab);
    float r = __fdividef(1.0f - e, 1.0f + e);
    return copysignf(r, a);
}

// ---------------- K1: pre-GEMV partials (16 rows/thread-col, butterfly red) --
__global__ __launch_bounds__(256, 2) void k1_pre_moments(const float* __restrict__ x,
                                                         const float* __restrict__ Wih,
                                                         const float* __restrict__ Wfc,
                                                         const float* __restrict__ bfc) {
    int b = blockIdx.x;
    int tid = threadIdx.x;

    if (b < PRE_BLOCKS) {
        int rt = b >> 2;                 // row tile (0..255)
        int c  = b & 3;                  // D-chunk (0..3)
        int t0 = rt * ROWS_PB;
        int i  = c * 256 + tid;          // float4 column index within row

        const float4* w0g = (const float4*)(Wih);
        const float4* w1g = (const float4*)(Wih + DD);
        float4 w0 = __ldg(&w0g[i]);
        float4 w1 = __ldg(&w1g[i]);

        // 16 independent streaming loads, front-batched for MLP
        float4 xv[ROWS_PB];
        const float4* xb = (const float4*)(x) + (size_t)t0 * (DD / 4) + i;
#pragma unroll
        for (int r = 0; r < ROWS_PB; r++) xv[r] = __ldcs(xb + (size_t)r * (DD / 4));

        // a[2r] = h0 contribution of row r, a[2r+1] = h1
        float a[32];
#pragma unroll
        for (int r = 0; r < ROWS_PB; r++) {
            float4 v = xv[r];
            a[2 * r]     = fmaf(v.x, w0.x, fmaf(v.y, w0.y, fmaf(v.z, w0.z, v.w * w0.w)));
            a[2 * r + 1] = fmaf(v.x, w1.x, fmaf(v.y, w1.y, fmaf(v.z, w1.z, v.w * w1.w)));
        }

        // butterfly multi-value reduce: 31 shfls; lane l ends holding slot l
        int lane = tid & 31;
#pragma unroll
        for (int o = 16; o; o >>= 1) {
#pragma unroll
            for (int j = 0; j < o; j++) {
                bool hi = (lane & o);
                float pass = hi ? a[j] : a[j + o];
                float recv = __shfl_xor_sync(0xffffffffu, pass, o);
                a[j] = (hi ? a[j + o] : a[j]) + recv;
            }
        }

        __shared__ float sred[8][33];
        int wid = tid >> 5;
        sred[wid][lane] = a[0];
        __syncthreads();
        if (tid < 32) {
            float s = 0.f;
#pragma unroll
            for (int w = 0; w < 8; w++) s += sred[w][tid];
            // slot l = (row l>>1, h l&1): contiguous, coalesced 128B store
            g_part[((size_t)c * TT + t0) * 2 + tid] = s;
        }
    } else {
        // ---- moments partials: block (j, vc), each covers V/4 elements ----
        int m = b - PRE_BLOCKS;
        int j  = m >> 2;                 // 0..10
        int vc = m & 3;                  // 0..3
        float acc[11];
#pragma unroll
        for (int k = 0; k < 11; k++) acc[k] = 0.f;

        int vbeg = vc * (VV / 4), vend = vbeg + (VV / 4);
        for (int v = vbeg + tid; v < vend; v += 256) {
            float2 w = *(const float2*)(Wfc + 2 * v);
            float p = __expf(bfc[v]);
#pragma unroll
            for (int a2 = 0; a2 < 10; a2++) {
                if (a2 < j) p *= w.x;
            }
#pragma unroll
            for (int k = 0; k < 11; k++) {
                acc[k] += p;
                p *= w.y;
            }
        }
        __shared__ float sredm[8][11];
#pragma unroll
        for (int k = 0; k < 11; k++) {
#pragma unroll
            for (int o = 16; o; o >>= 1)
                acc[k] += __shfl_down_sync(0xffffffffu, acc[k], o);
        }
        if ((tid & 31) == 0) {
#pragma unroll
            for (int k = 0; k < 11; k++) sredm[tid >> 5][k] = acc[k];
        }
        __syncthreads();
        if (tid < 11) {
            float tot = 0.f;
#pragma unroll
            for (int w = 0; w < 8; w++) tot += sredm[w][tid];
            g_Cm[vc * 121 + j * 11 + tid] = tot * c_invfact[j] * c_invfact[tid];
        }
    }
}

// ---------------- K2: sum partials + biases, segmented scan in SMEM ----------
__global__ __launch_bounds__(1024) void k2_scan(const float* __restrict__ Whh,
                                                const float* __restrict__ bih,
                                                const float* __restrict__ bhh) {
    __shared__ float sp0[TT];
    __shared__ float sp1[TT];
    int tid = threadIdx.x;
    float c0 = bih[0] + bhh[0];
    float c1 = bih[1] + bhh[1];
    for (int i = tid; i < TT; i += 1024) {
        float p0 = c0, p1 = c1;
#pragma unroll
        for (int c = 0; c < NCHUNK; c++) {
            p0 += g_part[((size_t)c * TT + i) * 2 + 0];
            p1 += g_part[((size_t)c * TT + i) * 2 + 1];
        }
        sp0[i] = p0;
        sp1[i] = p1;
    }
    __syncthreads();

    float W00 = Whh[0], W01 = Whh[1], W10 = Whh[2], W11 = Whh[3];
    float th0 = 9.2f + fabsf(W00) + fabsf(W01);
    float th1 = 9.2f + fabsf(W10) + fabsf(W11);

#pragma unroll
    for (int k = 0; k < 5; k++) {
        int idx = tid + k * 1024;           // starter index 0..TT
        if (k == 4 && tid != 0) break;      // only thread 0 handles idx==TT
        if (k == 4) idx = TT;

        float h0, h1;
        int t;
        if (idx == 0) {
            h0 = 0.f; h1 = 0.f; t = 0;
        } else {
            int r = idx - 1;
            float p0 = sp0[r], p1 = sp1[r];
            if (!(fabsf(p0) > th0 && fabsf(p1) > th1)) continue;  // not a reset point
            h0 = copysignf(1.0f, p0);   // saturated: tanh == +-1.0f exactly
            h1 = copysignf(1.0f, p1);
            g_h0[r] = h0;
            g_h1[r] = h1;
            t = r + 1;
        }
        while (t < TT) {
            float p0 = sp0[t], p1 = sp1[t];
            if (fabsf(p0) > th0 && fabsf(p1) > th1) break;  // next reset owns t
            float a0 = fmaf(W01, h1, fmaf(W00, h0, p0));
            float a1 = fmaf(W11, h1, fmaf(W10, h0, p1));
            h0 = tanh_acc(a0);
            h1 = tanh_acc(a1);
            g_h0[t] = h0;
            g_h1[t] = h1;
            t++;
        }
    }
}

// ---------------- K3: logits (HBM-write bound, 32-row tiles) + loss fused ----
__global__ __launch_bounds__(256) void k3_logits_loss(const float* __restrict__ Wfc,
                                                      const float* __restrict__ bfc,
                                                      const int* __restrict__ tgt_raw,
                                                      float* __restrict__ out,
                                                      long long loss_idx,
                                                      int n_logit_blocks) {
    int b = blockIdx.x;
    int tid = threadIdx.x;

    if (b < n_logit_blocks) {
        // ------------- logits -------------
        __shared__ float sh0[32], sh1[32];
        int tb = (b & 127) * 32;
        if (tid < 32) {
            sh0[tid] = g_h0[tb + tid];
            sh1[tid] = g_h1[tb + tid];
        }
        __syncthreads();
        float h0r[32], h1r[32];
#pragma unroll
        for (int r = 0; r < 32; r++) { h0r[r] = sh0[r]; h1r[r] = sh1[r]; }

        const int vbeg = (b >> 7) * 4000;
        const int vend = vbeg + 4000;
        for (int v = vbeg + tid * 4; v < vend; v += 1024) {
            float4 wa = *(const float4*)(Wfc + 2 * v);      // w0,w1 of v, v+1
            float4 wb = *(const float4*)(Wfc + 2 * v + 4);  // w0,w1 of v+2, v+3
            float4 bb = *(const float4*)(bfc + v);
            float* op = out + (size_t)tb * VV + v;
#pragma unroll
            for (int r = 0; r < 32; r++) {
                float4 o;
                o.x = fmaf(h0r[r], wa.x, fmaf(h1r[r], wa.y, bb.x));
                o.y = fmaf(h0r[r], wa.z, fmaf(h1r[r], wa.w, bb.y));
                o.z = fmaf(h0r[r], wb.x, fmaf(h1r[r], wb.y, bb.z));
                o.w = fmaf(h0r[r], wb.z, fmaf(h1r[r], wb.w, bb.w));
                __stcs((float4*)(op + (size_t)r * VV), o);
            }
        }
    } else {
        // ------------- loss (runs concurrently with logits blocks) -------------
        __shared__ float sC[121];
        if (tid < 121)
            sC[tid] = g_Cm[tid] + g_Cm[121 + tid] + g_Cm[242 + tid] + g_Cm[363 + tid];

        // detect int64 vs int32 targets: int64 (LE) => all odd 32-bit words of
        // the first 4096 words are zero (values < 32000). OOB-safe either way.
        int local = 0;
        for (int i = tid; i < TT / 2; i += 256) local |= tgt_raw[2 * i + 1];
        int nz = __syncthreads_or(local);
        int is64 = (nz == 0);

        float acc = 0.f;
#pragma unroll
        for (int r = 0; r < 16; r++) {
            int t = r * 256 + tid;
            float h0 = g_h0[t];
            float h1 = g_h1[t];
            // sumexp(h) = sum_{j,k<=10} C_jk h0^j h1^k (double Horner)
            float S = 0.f;
#pragma unroll
            for (int j = 10; j >= 0; j--) {
                const float* row = &sC[j * 11];
                float inner = row[10];
#pragma unroll
                for (int k = 9; k >= 0; k--) inner = fmaf(inner, h1, row[k]);
                S = fmaf(S, h0, inner);
            }
            int g = is64 ? tgt_raw[2 * t] : tgt_raw[t];
            float lt = fmaf(h0, Wfc[2 * g], fmaf(h1, Wfc[2 * g + 1], bfc[g]));
            acc += logf(S) - lt;
        }

#pragma unroll
        for (int o = 16; o; o >>= 1) acc += __shfl_down_sync(0xffffffffu, acc, o);
        __shared__ float s[8];
        if ((tid & 31) == 0) s[tid >> 5] = acc;
        __syncthreads();
        if (tid == 0) {
            float tot = 0.f;
#pragma unroll
            for (int w = 0; w < 8; w++) tot += s[w];
            if (loss_idx >= 0) out[loss_idx] = tot * (1.0f / TT);
        }
    }
}

// ---------------- launch ----------------
extern "C" void kernel_launch(void* const* d_in, const int* in_sizes, int n_in,
                              void* d_out, int out_size) {
    const float* x       = (const float*)d_in[0];
    const int*   targets = (const int*)d_in[1];   // int32 or int64, detected on device
    const float* Wih     = (const float*)d_in[2];
    const float* bih     = (const float*)d_in[3];
    const float* Whh     = (const float*)d_in[4];
    const float* bhh     = (const float*)d_in[5];
    const float* Wfc     = (const float*)d_in[6];
    const float* bfc     = (const float*)d_in[7];
    float* out = (float*)d_out;

    const long long logits_elems = (long long)TT * VV;

    k1_pre_moments<<<PRE_BLOCKS + MOM_BLOCKS, 256>>>(x, Wih, Wfc, bfc);
    k2_scan<<<1, 1024>>>(Whh, bih, bhh);

    int n_logit_blocks = ((long long)out_size >= logits_elems) ? 1024 : 0;
    long long loss_idx = -1;
    if ((long long)out_size > logits_elems) loss_idx = logits_elems;  // logits + loss
    else if (out_size == 1) loss_idx = 0;                             // loss only
    k3_logits_loss<<<n_logit_blocks + 1, 256>>>(Wfc, bfc, targets, out,
                                                loss_idx, n_logit_blocks);
}